// round 8
// baseline (speedup 1.0000x reference)
#include <cuda_runtime.h>
#include <math.h>

// Problem constants (fixed by setup_inputs)
#define BATCH   8
#define CHAN    256
#define NPIX    16384        // 128*128
#define NITER   16
#define TILE    64           // pixels per tile
#define NTHR    256
#define NT      (NPIX/TILE)  // 256 tiles per batch

// d_out layout: reprVecs [16,8,256] | sims [16,8,16384] | selpos [8,16384]
#define OFF_SIMS   (NITER*BATCH*CHAN)
#define OFF_SELPOS (OFF_SIMS + NITER*BATCH*NPIX)

// Scratch (__device__ globals; allocations forbidden)
__device__ float g_score[BATCH*NPIX];
// candidate buffers DOUBLE-BUFFERED by iteration parity: a block in launch i
// reads slot (i-1)&1 while writing slot i&1 -> no same-launch read/write race.
__device__ float g_cand_val[2][BATCH*NT];
__device__ int   g_cand_idx[2][BATCH*NT];
__device__ int   g_selind[NITER*BATCH];
// per-(iter,batch,tile) partials, reduced once at the end (off critical path)
__device__ float g_rpart[NITER*BATCH*NT*CHAN];   // 32 MB
__device__ float g_spart[NITER*BATCH*NT];        // 512 KB

// ---------------------------------------------------------------------------
// Main kernel: one block per (64-pixel tile, batch) = 2048 blocks, 3/SM.
// Prologue: every block redundantly reduces the 256 per-tile argmax candidates
// from the previous launch (read-only buffer) and gathers its rv (L2-served).
// Pass 1: stream tile from gmem; compute (x-rv)^2 partials in registers WHILE
// staging to smem with STS.128 (no separate distance LDS pass).
// Pass 2 (repr): warp-per-channel coalesced LDS.64 + shfl-xor reduce.
extern "C" __global__ void __launch_bounds__(NTHR, 3)
main_kernel(int iter, const float* __restrict__ x,
            float* __restrict__ sims_out)
{
    extern __shared__ float s_x[];             // [CHAN][TILE] = 64 KB
    __shared__ float s_rv[CHAN];
    __shared__ float s_pd[16][TILE];
    __shared__ float s_sim[TILE];
    __shared__ float s_red[2];
    __shared__ float s_redv[2];
    __shared__ int   s_redi[2];
    __shared__ float s_cv[8];
    __shared__ int   s_ci[8];
    __shared__ int   s_ind;

    const int b    = blockIdx.y;
    const int tile = blockIdx.x;
    const int n0   = tile * TILE;
    const int tid  = threadIdx.x;
    const int lane = tid & 31;
    const int w    = tid >> 5;
    const int rd   = (iter + 1) & 1;           // prev iteration's slot
    const int wr   = iter & 1;                 // this iteration's slot
    const float* __restrict__ xb = x + (size_t)b * CHAN * NPIX;

    // ---- prologue: pick index (argmax of prev scores, or N/2 at iter 0) ----
    if (iter == 0) {
        if (tid == 0) s_ind = NPIX / 2;
    } else {
        float v  = g_cand_val[rd][b*NT + tid]; // NT == NTHR
        int   ix = g_cand_idx[rd][b*NT + tid];
        #pragma unroll
        for (int o = 16; o; o >>= 1) {
            float v2 = __shfl_down_sync(0xffffffffu, v, o);
            int   i2 = __shfl_down_sync(0xffffffffu, ix, o);
            if (v2 > v || (v2 == v && i2 < ix)) { v = v2; ix = i2; }
        }
        if (lane == 0) { s_cv[w] = v; s_ci[w] = ix; }
        __syncthreads();
        if (tid == 0) {
            float bv = s_cv[0]; int bi = s_ci[0];
            #pragma unroll
            for (int k = 1; k < 8; ++k) {
                float v2 = s_cv[k]; int i2 = s_ci[k];
                if (v2 > bv || (v2 == bv && i2 < bi)) { bv = v2; bi = i2; }
            }
            s_ind = bi;
        }
    }
    __syncthreads();
    const int ind = s_ind;
    // rv gather: one strided load per thread (L2-hit after first block of b)
    s_rv[tid] = xb[(size_t)tid * NPIX + ind];
    if (tile == 0 && tid == 0) g_selind[iter * BATCH + b] = ind;
    __syncthreads();

    // ---- pass 1: stream tile, fused distance partials + STS.128 staging ----
    {
        const int k4 = tid & 15;               // pixel quad [4k4, 4k4+4)
        const int r  = tid >> 4;               // channel residue (0..15)
        const float* gp = xb + (size_t)r * NPIX + n0 + k4 * 4;
        float* sp = s_x + r * TILE + k4 * 4;
        float a0 = 0.f, a1 = 0.f, a2 = 0.f, a3 = 0.f;
        #pragma unroll 4
        for (int i = 0; i < 16; ++i) {
            const int c = r + 16 * i;
            float4 v = *(const float4*)(gp + (size_t)(16 * i) * NPIX);
            *(float4*)(sp + 16 * i * TILE) = v;
            float rv = s_rv[c];
            float d0 = v.x - rv, d1 = v.y - rv, d2 = v.z - rv, d3 = v.w - rv;
            a0 = fmaf(d0, d0, a0); a1 = fmaf(d1, d1, a1);
            a2 = fmaf(d2, d2, a2); a3 = fmaf(d3, d3, a3);
        }
        *(float4*)(&s_pd[r][k4 * 4]) = make_float4(a0, a1, a2, a3);
    }
    __syncthreads();

    // ---- sim, score update, per-tile sumsim + argmax candidate ----
    if (tid < TILE) {
        float ssq = 0.f;
        #pragma unroll
        for (int r = 0; r < 16; ++r) ssq += s_pd[r][tid];
        float d   = sqrtf(ssq + 1e-12f);
        float sim = __expf(-0.05f * d);
        s_sim[tid] = sim;
        const int np = n0 + tid;
        sims_out[((size_t)iter * BATCH + b) * NPIX + np] = sim;
        float sc = 1.0f - sim;
        if (iter > 0) sc *= g_score[(size_t)b * NPIX + np];
        g_score[(size_t)b * NPIX + np] = sc;

        float ws = sim;
        #pragma unroll
        for (int o = 16; o; o >>= 1) ws += __shfl_down_sync(0xffffffffu, ws, o);
        if (lane == 0) s_red[w] = ws;

        float bv = sc; int bi = np;
        #pragma unroll
        for (int o = 16; o; o >>= 1) {
            float v2 = __shfl_down_sync(0xffffffffu, bv, o);
            int   i2 = __shfl_down_sync(0xffffffffu, bi, o);
            if (v2 > bv || (v2 == bv && i2 < bi)) { bv = v2; bi = i2; }
        }
        if (lane == 0) { s_redv[w] = bv; s_redi[w] = bi; }
    }
    __syncthreads();
    if (tid == 0) {
        g_spart[((size_t)iter * BATCH + b) * NT + tile] = s_red[0] + s_red[1];
        float v0 = s_redv[0], v1 = s_redv[1];
        int   i0 = s_redi[0], i1 = s_redi[1];
        bool take1 = (v1 > v0) || (v1 == v0 && i1 < i0);
        g_cand_val[wr][b*NT + tile] = take1 ? v1 : v0;
        g_cand_idx[wr][b*NT + tile] = take1 ? i1 : i0;
    }

    // ---- pass 2: repr partials. warp w owns channels [32w, 32w+32) --------
    {
        const float sx = s_sim[lane * 2];
        const float sy = s_sim[lane * 2 + 1];
        float keep = 0.f;
        #pragma unroll 8
        for (int cc = 0; cc < 32; ++cc) {
            const int c = w * 32 + cc;
            float2 v = *(const float2*)(s_x + c * TILE + lane * 2);
            float a = fmaf(v.y, sy, v.x * sx);
            #pragma unroll
            for (int o = 16; o; o >>= 1)
                a += __shfl_xor_sync(0xffffffffu, a, o);
            if (lane == cc) keep = a;          // channel c == w*32+lane == tid
        }
        g_rpart[(((size_t)iter * BATCH + b) * NT + tile) * CHAN + tid] = keep;
    }
}

// ---------------------------------------------------------------------------
// Final kernel, grid = 136 blocks:
//   blocks [0,128): (iter,batch) -> reduce 256 tile partials, write reprVecs
//   blocks [128,136): batch -> zero selpos slice + scatter 16 recorded picks
__global__ void final_kernel(float* __restrict__ repr_out,
                             float* __restrict__ selpos) {
    const int blk = blockIdx.x;
    const int tid = threadIdx.x;

    if (blk < NITER * BATCH) {
        __shared__ float s_sp[NTHR];
        s_sp[tid] = g_spart[(size_t)blk * NT + tid];
        __syncthreads();
        for (int s = NTHR/2; s > 0; s >>= 1) {
            if (tid < s) s_sp[tid] += s_sp[tid + s];
            __syncthreads();
        }
        const float inv = 1.0f / s_sp[0];
        const float* rp = g_rpart + (size_t)blk * NT * CHAN;
        float a0 = 0.f, a1 = 0.f, a2 = 0.f, a3 = 0.f;
        #pragma unroll 4
        for (int t = 0; t < NT; t += 4) {
            a0 += rp[(t  ) * CHAN + tid];
            a1 += rp[(t+1) * CHAN + tid];
            a2 += rp[(t+2) * CHAN + tid];
            a3 += rp[(t+3) * CHAN + tid];
        }
        repr_out[(size_t)blk * CHAN + tid] = ((a0 + a1) + (a2 + a3)) * inv;
    } else {
        const int b = blk - NITER * BATCH;
        for (int k = tid; k < NPIX; k += NTHR)
            selpos[(size_t)b * NPIX + k] = 0.0f;
        __syncthreads();
        if (tid == 0) {
            #pragma unroll
            for (int t = 0; t < NITER; ++t)
                selpos[(size_t)b * NPIX + g_selind[t * BATCH + b]] += 1.0f;
        }
    }
}

// ---------------------------------------------------------------------------
extern "C" void kernel_launch(void* const* d_in, const int* in_sizes, int n_in,
                              void* d_out, int out_size) {
    const float* x = (const float*)d_in[0];
    float* out      = (float*)d_out;
    float* repr_out = out;
    float* sims_out = out + OFF_SIMS;
    float* selpos   = out + OFF_SELPOS;

    cudaFuncSetAttribute(main_kernel,
                         cudaFuncAttributeMaxDynamicSharedMemorySize,
                         CHAN * TILE * (int)sizeof(float));

    dim3 grid(NT, BATCH);
    for (int i = 0; i < NITER; ++i)
        main_kernel<<<grid, NTHR, CHAN * TILE * sizeof(float)>>>(i, x, sims_out);
    final_kernel<<<NITER * BATCH + BATCH, NTHR>>>(repr_out, selpos);
}

// round 9
// speedup vs baseline: 1.2705x; 1.2705x over previous
#include <cuda_runtime.h>
#include <math.h>

// Problem constants (fixed by setup_inputs)
#define BATCH   8
#define CHAN    256
#define NPIX    16384        // 128*128
#define NITER   16
#define TILE    64           // pixels per tile
#define NTHR    256
#define NT      (NPIX/TILE)  // 256 tiles per batch

// d_out layout: reprVecs [16,8,256] | sims [16,8,16384] | selpos [8,16384]
#define OFF_SIMS   (NITER*BATCH*CHAN)
#define OFF_SELPOS (OFF_SIMS + NITER*BATCH*NPIX)

// Scratch (__device__ globals; allocations forbidden)
__device__ float g_score[BATCH*NPIX];
// candidate buffers double-buffered by iteration parity (no same-launch race)
__device__ float g_cand_val[2][BATCH*NT];
__device__ int   g_cand_idx[2][BATCH*NT];
__device__ int   g_selind[NITER*BATCH];
// per-(iter,batch,tile) partials, reduced once at the end (off critical path)
__device__ float g_rpart[NITER*BATCH*NT*CHAN];   // 32 MB
__device__ float g_spart[NITER*BATCH*NT];        // 512 KB

#define SRP 17   // padded stride for repr partial smem (conflict-free)

// ---------------------------------------------------------------------------
// Main kernel: one block per (64-pixel tile, batch) = 2048 blocks.
// NO smem tile: pass 1 streams x from gmem (16 independent float4 LDGs per
// thread) computing distance partials; pass 2 re-reads the same 64 KB (L2-hot)
// for the sim-weighted repr partials. Small smem -> 4+ blocks/SM.
// Thread mapping: k4 = tid&15 (pixel quad), r = tid>>4 (channel residue);
// thread covers channels {r+16i} for its 4 pixels.
extern "C" __global__ void __launch_bounds__(NTHR, 4)
main_kernel(int iter, const float* __restrict__ x,
            float* __restrict__ sims_out)
{
    __shared__ float s_rv[CHAN];
    __shared__ float s_pd[16][TILE];
    __shared__ float s_sim[TILE];
    __shared__ float s_rp[CHAN * SRP];         // repr partials [c][k4], padded
    __shared__ float s_red[2];
    __shared__ float s_redv[2];
    __shared__ int   s_redi[2];
    __shared__ float s_cv[8];
    __shared__ int   s_ci[8];
    __shared__ int   s_ind;

    const int b    = blockIdx.y;
    const int tile = blockIdx.x;
    const int n0   = tile * TILE;
    const int tid  = threadIdx.x;
    const int lane = tid & 31;
    const int w    = tid >> 5;
    const int k4   = tid & 15;
    const int r    = tid >> 4;
    const int rd   = (iter + 1) & 1;
    const int wr   = iter & 1;
    const float* __restrict__ xb = x + (size_t)b * CHAN * NPIX;

    // ---- prologue: pick index (argmax of prev scores, or N/2 at iter 0) ----
    if (iter == 0) {
        if (tid == 0) s_ind = NPIX / 2;
    } else {
        float v  = g_cand_val[rd][b*NT + tid]; // NT == NTHR
        int   ix = g_cand_idx[rd][b*NT + tid];
        #pragma unroll
        for (int o = 16; o; o >>= 1) {
            float v2 = __shfl_down_sync(0xffffffffu, v, o);
            int   i2 = __shfl_down_sync(0xffffffffu, ix, o);
            if (v2 > v || (v2 == v && i2 < ix)) { v = v2; ix = i2; }
        }
        if (lane == 0) { s_cv[w] = v; s_ci[w] = ix; }
        __syncthreads();
        if (tid == 0) {
            float bv = s_cv[0]; int bi = s_ci[0];
            #pragma unroll
            for (int k = 1; k < 8; ++k) {
                float v2 = s_cv[k]; int i2 = s_ci[k];
                if (v2 > bv || (v2 == bv && i2 < bi)) { bv = v2; bi = i2; }
            }
            s_ind = bi;
        }
    }
    __syncthreads();
    const int ind = s_ind;
    // rv gather: one strided load per thread (L2-hit after first block of b)
    s_rv[tid] = xb[(size_t)tid * NPIX + ind];
    if (tile == 0 && tid == 0) g_selind[iter * BATCH + b] = ind;
    __syncthreads();

    const float* gp = xb + (size_t)r * NPIX + n0 + k4 * 4;

    // ---- pass 1: stream tile, distance partials in registers ----
    {
        float a0 = 0.f, a1 = 0.f, a2 = 0.f, a3 = 0.f;
        #pragma unroll
        for (int i = 0; i < 16; ++i) {
            float4 v = *(const float4*)(gp + (size_t)(16 * i) * NPIX);
            float rv = s_rv[r + 16 * i];
            float d0 = v.x - rv, d1 = v.y - rv, d2 = v.z - rv, d3 = v.w - rv;
            a0 = fmaf(d0, d0, a0); a1 = fmaf(d1, d1, a1);
            a2 = fmaf(d2, d2, a2); a3 = fmaf(d3, d3, a3);
        }
        *(float4*)(&s_pd[r][k4 * 4]) = make_float4(a0, a1, a2, a3);
    }
    __syncthreads();

    // ---- sim, score update, per-tile sumsim + argmax candidate ----
    if (tid < TILE) {
        float ssq = 0.f;
        #pragma unroll
        for (int rr = 0; rr < 16; ++rr) ssq += s_pd[rr][tid];
        float d   = sqrtf(ssq + 1e-12f);
        float sim = __expf(-0.05f * d);
        s_sim[tid] = sim;
        const int np = n0 + tid;
        sims_out[((size_t)iter * BATCH + b) * NPIX + np] = sim;
        float sc = 1.0f - sim;
        if (iter > 0) sc *= g_score[(size_t)b * NPIX + np];
        g_score[(size_t)b * NPIX + np] = sc;

        float ws = sim;
        #pragma unroll
        for (int o = 16; o; o >>= 1) ws += __shfl_down_sync(0xffffffffu, ws, o);
        if (lane == 0) s_red[w] = ws;

        float bv = sc; int bi = np;
        #pragma unroll
        for (int o = 16; o; o >>= 1) {
            float v2 = __shfl_down_sync(0xffffffffu, bv, o);
            int   i2 = __shfl_down_sync(0xffffffffu, bi, o);
            if (v2 > bv || (v2 == bv && i2 < bi)) { bv = v2; bi = i2; }
        }
        if (lane == 0) { s_redv[w] = bv; s_redi[w] = bi; }
    }
    __syncthreads();
    if (tid == 0) {
        g_spart[((size_t)iter * BATCH + b) * NT + tile] = s_red[0] + s_red[1];
        float v0 = s_redv[0], v1 = s_redv[1];
        int   i0 = s_redi[0], i1 = s_redi[1];
        bool take1 = (v1 > v0) || (v1 == v0 && i1 < i0);
        g_cand_val[wr][b*NT + tile] = take1 ? v1 : v0;
        g_cand_idx[wr][b*NT + tile] = take1 ? i1 : i0;
    }

    // ---- pass 2: re-read tile (L2-hot), repr partials ----
    {
        const float s0 = s_sim[k4 * 4 + 0];
        const float s1 = s_sim[k4 * 4 + 1];
        const float s2 = s_sim[k4 * 4 + 2];
        const float s3 = s_sim[k4 * 4 + 3];
        #pragma unroll
        for (int i = 0; i < 16; ++i) {
            float4 v = *(const float4*)(gp + (size_t)(16 * i) * NPIX);
            float p = fmaf(v.x, s0, v.y * s1) + fmaf(v.z, s2, v.w * s3);
            s_rp[(r + 16 * i) * SRP + k4] = p;
        }
    }
    __syncthreads();
    // thread tid == channel c: sum its 16 pixel-quad partials (conflict-free)
    {
        const float* rp = s_rp + tid * SRP;
        float a0 = 0.f, a1 = 0.f, a2 = 0.f, a3 = 0.f;
        #pragma unroll
        for (int k = 0; k < 16; k += 4) {
            a0 += rp[k]; a1 += rp[k+1]; a2 += rp[k+2]; a3 += rp[k+3];
        }
        g_rpart[(((size_t)iter * BATCH + b) * NT + tile) * CHAN + tid] =
            (a0 + a1) + (a2 + a3);
    }
}

// ---------------------------------------------------------------------------
// Final kernel, grid = 136 blocks:
//   blocks [0,128): (iter,batch) -> reduce 256 tile partials, write reprVecs
//   blocks [128,136): batch -> zero selpos slice + scatter 16 recorded picks
__global__ void final_kernel(float* __restrict__ repr_out,
                             float* __restrict__ selpos) {
    const int blk = blockIdx.x;
    const int tid = threadIdx.x;

    if (blk < NITER * BATCH) {
        __shared__ float s_sp[NTHR];
        s_sp[tid] = g_spart[(size_t)blk * NT + tid];
        __syncthreads();
        for (int s = NTHR/2; s > 0; s >>= 1) {
            if (tid < s) s_sp[tid] += s_sp[tid + s];
            __syncthreads();
        }
        const float inv = 1.0f / s_sp[0];
        const float* rp = g_rpart + (size_t)blk * NT * CHAN;
        float a0 = 0.f, a1 = 0.f, a2 = 0.f, a3 = 0.f;
        #pragma unroll 4
        for (int t = 0; t < NT; t += 4) {
            a0 += rp[(t  ) * CHAN + tid];
            a1 += rp[(t+1) * CHAN + tid];
            a2 += rp[(t+2) * CHAN + tid];
            a3 += rp[(t+3) * CHAN + tid];
        }
        repr_out[(size_t)blk * CHAN + tid] = ((a0 + a1) + (a2 + a3)) * inv;
    } else {
        const int b = blk - NITER * BATCH;
        for (int k = tid; k < NPIX; k += NTHR)
            selpos[(size_t)b * NPIX + k] = 0.0f;
        __syncthreads();
        if (tid == 0) {
            #pragma unroll
            for (int t = 0; t < NITER; ++t)
                selpos[(size_t)b * NPIX + g_selind[t * BATCH + b]] += 1.0f;
        }
    }
}

// ---------------------------------------------------------------------------
extern "C" void kernel_launch(void* const* d_in, const int* in_sizes, int n_in,
                              void* d_out, int out_size) {
    const float* x = (const float*)d_in[0];
    float* out      = (float*)d_out;
    float* repr_out = out;
    float* sims_out = out + OFF_SIMS;
    float* selpos   = out + OFF_SELPOS;

    dim3 grid(NT, BATCH);
    for (int i = 0; i < NITER; ++i)
        main_kernel<<<grid, NTHR>>>(i, x, sims_out);
    final_kernel<<<NITER * BATCH + BATCH, NTHR>>>(repr_out, selpos);
}

// round 11
// speedup vs baseline: 1.4828x; 1.1672x over previous
#include <cuda_runtime.h>
#include <math.h>

// Problem constants (fixed by setup_inputs)
#define BATCH   8
#define CHAN    256
#define NPIX    16384        // 128*128
#define NITER   16
#define TILE    64           // pixels per tile
#define NTHR    256
#define NT      (NPIX/TILE)  // 256 tiles per batch

// d_out layout: reprVecs [16,8,256] | sims [16,8,16384] | selpos [8,16384]
#define OFF_SIMS   (NITER*BATCH*CHAN)
#define OFF_SELPOS (OFF_SIMS + NITER*BATCH*NPIX)

// Scratch (__device__ globals; allocations forbidden)
__device__ float g_score[BATCH*NPIX];
// candidate buffers double-buffered by iteration parity (no same-launch race)
__device__ float g_cand_val[2][BATCH*NT];
__device__ int   g_cand_idx[2][BATCH*NT];
__device__ int   g_selind[NITER*BATCH];
// per-(iter,batch,tile) partials, reduced once at the end (off critical path)
__device__ float g_rpart[NITER*BATCH*NT*CHAN];   // 32 MB
__device__ float g_spart[NITER*BATCH*NT];        // 512 KB

#define SRP 17   // padded stride for repr partial smem (conflict-free)

// ---- L2 eviction-priority hinted accessors --------------------------------
// x (134 MB) vs L2 (126 MB): plain streaming thrashes LRU -> full DRAM reread
// every iteration. createpolicy(evict_last) + cache_hint pins x lines;
// single-use streams are written with .cs.
__device__ __forceinline__ unsigned long long mk_policy() {
    unsigned long long pol;
    asm("createpolicy.fractional.L2::evict_last.b64 %0, 1.0;" : "=l"(pol));
    return pol;
}
__device__ __forceinline__ float4 ldg_x4(const float* p, unsigned long long pol) {
    float4 v;
    asm volatile("ld.global.nc.L2::cache_hint.v4.f32 {%0,%1,%2,%3}, [%4], %5;"
                 : "=f"(v.x), "=f"(v.y), "=f"(v.z), "=f"(v.w)
                 : "l"(p), "l"(pol));
    return v;
}
__device__ __forceinline__ float ldg_x1(const float* p, unsigned long long pol) {
    float v;
    asm volatile("ld.global.nc.L2::cache_hint.f32 %0, [%1], %2;"
                 : "=f"(v) : "l"(p), "l"(pol));
    return v;
}
__device__ __forceinline__ void stg_cs(float* p, float v) {
    asm volatile("st.global.cs.f32 [%0], %1;" :: "l"(p), "f"(v));
}

// ---------------------------------------------------------------------------
// Main kernel: one block per (64-pixel tile, batch) = 2048 blocks, 4/SM.
// No smem tile: pass 1 streams x (16 independent float4 LDGs per thread) for
// distance partials; pass 2 re-reads the same 64 KB (L2-pinned) for repr.
extern "C" __global__ void __launch_bounds__(NTHR, 4)
main_kernel(int iter, const float* __restrict__ x,
            float* __restrict__ sims_out)
{
    __shared__ float s_rv[CHAN];
    __shared__ float s_pd[16][TILE];
    __shared__ float s_sim[TILE];
    __shared__ float s_rp[CHAN * SRP];         // repr partials [c][k4], padded
    __shared__ float s_red[2];
    __shared__ float s_redv[2];
    __shared__ int   s_redi[2];
    __shared__ float s_cv[8];
    __shared__ int   s_ci[8];
    __shared__ int   s_ind;

    const int b    = blockIdx.y;
    const int tile = blockIdx.x;
    const int n0   = tile * TILE;
    const int tid  = threadIdx.x;
    const int lane = tid & 31;
    const int w    = tid >> 5;
    const int k4   = tid & 15;
    const int r    = tid >> 4;
    const int rd   = (iter + 1) & 1;
    const int wr   = iter & 1;
    const unsigned long long pol = mk_policy();
    const float* __restrict__ xb = x + (size_t)b * CHAN * NPIX;

    // ---- prologue: pick index (argmax of prev scores, or N/2 at iter 0) ----
    if (iter == 0) {
        if (tid == 0) s_ind = NPIX / 2;
    } else {
        float v  = g_cand_val[rd][b*NT + tid]; // NT == NTHR
        int   ix = g_cand_idx[rd][b*NT + tid];
        #pragma unroll
        for (int o = 16; o; o >>= 1) {
            float v2 = __shfl_down_sync(0xffffffffu, v, o);
            int   i2 = __shfl_down_sync(0xffffffffu, ix, o);
            if (v2 > v || (v2 == v && i2 < ix)) { v = v2; ix = i2; }
        }
        if (lane == 0) { s_cv[w] = v; s_ci[w] = ix; }
        __syncthreads();
        if (tid == 0) {
            float bv = s_cv[0]; int bi = s_ci[0];
            #pragma unroll
            for (int k = 1; k < 8; ++k) {
                float v2 = s_cv[k]; int i2 = s_ci[k];
                if (v2 > bv || (v2 == bv && i2 < bi)) { bv = v2; bi = i2; }
            }
            s_ind = bi;
        }
    }
    __syncthreads();
    const int ind = s_ind;
    // rv gather: one strided load per thread (L2-pinned x line)
    s_rv[tid] = ldg_x1(xb + (size_t)tid * NPIX + ind, pol);
    if (tile == 0 && tid == 0) g_selind[iter * BATCH + b] = ind;
    __syncthreads();

    const float* gp = xb + (size_t)r * NPIX + n0 + k4 * 4;

    // ---- pass 1: stream tile, distance partials in registers ----
    {
        float a0 = 0.f, a1 = 0.f, a2 = 0.f, a3 = 0.f;
        #pragma unroll
        for (int i = 0; i < 16; ++i) {
            float4 v = ldg_x4(gp + (size_t)(16 * i) * NPIX, pol);
            float rv = s_rv[r + 16 * i];
            float d0 = v.x - rv, d1 = v.y - rv, d2 = v.z - rv, d3 = v.w - rv;
            a0 = fmaf(d0, d0, a0); a1 = fmaf(d1, d1, a1);
            a2 = fmaf(d2, d2, a2); a3 = fmaf(d3, d3, a3);
        }
        *(float4*)(&s_pd[r][k4 * 4]) = make_float4(a0, a1, a2, a3);
    }
    __syncthreads();

    // ---- sim, score update, per-tile sumsim + argmax candidate ----
    if (tid < TILE) {
        float ssq = 0.f;
        #pragma unroll
        for (int rr = 0; rr < 16; ++rr) ssq += s_pd[rr][tid];
        float d   = sqrtf(ssq + 1e-12f);
        float sim = __expf(-0.05f * d);
        s_sim[tid] = sim;
        const int np = n0 + tid;
        stg_cs(sims_out + ((size_t)iter * BATCH + b) * NPIX + np, sim);
        float sc = 1.0f - sim;
        if (iter > 0) sc *= g_score[(size_t)b * NPIX + np];
        g_score[(size_t)b * NPIX + np] = sc;

        float ws = sim;
        #pragma unroll
        for (int o = 16; o; o >>= 1) ws += __shfl_down_sync(0xffffffffu, ws, o);
        if (lane == 0) s_red[w] = ws;

        float bv = sc; int bi = np;
        #pragma unroll
        for (int o = 16; o; o >>= 1) {
            float v2 = __shfl_down_sync(0xffffffffu, bv, o);
            int   i2 = __shfl_down_sync(0xffffffffu, bi, o);
            if (v2 > bv || (v2 == bv && i2 < bi)) { bv = v2; bi = i2; }
        }
        if (lane == 0) { s_redv[w] = bv; s_redi[w] = bi; }
    }
    __syncthreads();
    if (tid == 0) {
        g_spart[((size_t)iter * BATCH + b) * NT + tile] = s_red[0] + s_red[1];
        float v0 = s_redv[0], v1 = s_redv[1];
        int   i0 = s_redi[0], i1 = s_redi[1];
        bool take1 = (v1 > v0) || (v1 == v0 && i1 < i0);
        g_cand_val[wr][b*NT + tile] = take1 ? v1 : v0;
        g_cand_idx[wr][b*NT + tile] = take1 ? i1 : i0;
    }

    // ---- pass 2: re-read tile (L2-pinned), repr partials ----
    {
        const float s0 = s_sim[k4 * 4 + 0];
        const float s1 = s_sim[k4 * 4 + 1];
        const float s2 = s_sim[k4 * 4 + 2];
        const float s3 = s_sim[k4 * 4 + 3];
        #pragma unroll
        for (int i = 0; i < 16; ++i) {
            float4 v = ldg_x4(gp + (size_t)(16 * i) * NPIX, pol);
            float p = fmaf(v.x, s0, v.y * s1) + fmaf(v.z, s2, v.w * s3);
            s_rp[(r + 16 * i) * SRP + k4] = p;
        }
    }
    __syncthreads();
    // thread tid == channel c: sum its 16 pixel-quad partials (conflict-free)
    {
        const float* rp = s_rp + tid * SRP;
        float a0 = 0.f, a1 = 0.f, a2 = 0.f, a3 = 0.f;
        #pragma unroll
        for (int k = 0; k < 16; k += 4) {
            a0 += rp[k]; a1 += rp[k+1]; a2 += rp[k+2]; a3 += rp[k+3];
        }
        stg_cs(g_rpart + (((size_t)iter * BATCH + b) * NT + tile) * CHAN + tid,
               (a0 + a1) + (a2 + a3));
    }
}

// ---------------------------------------------------------------------------
// Final kernel, grid = 136 blocks:
//   blocks [0,128): (iter,batch) -> reduce 256 tile partials, write reprVecs
//   blocks [128,136): batch -> zero selpos slice + scatter 16 recorded picks
__global__ void final_kernel(float* __restrict__ repr_out,
                             float* __restrict__ selpos) {
    const int blk = blockIdx.x;
    const int tid = threadIdx.x;

    if (blk < NITER * BATCH) {
        __shared__ float s_sp[NTHR];
        s_sp[tid] = g_spart[(size_t)blk * NT + tid];
        __syncthreads();
        for (int s = NTHR/2; s > 0; s >>= 1) {
            if (tid < s) s_sp[tid] += s_sp[tid + s];
            __syncthreads();
        }
        const float inv = 1.0f / s_sp[0];
        const float* rp = g_rpart + (size_t)blk * NT * CHAN;
        float a0 = 0.f, a1 = 0.f, a2 = 0.f, a3 = 0.f;
        #pragma unroll 4
        for (int t = 0; t < NT; t += 4) {
            a0 += rp[(t  ) * CHAN + tid];
            a1 += rp[(t+1) * CHAN + tid];
            a2 += rp[(t+2) * CHAN + tid];
            a3 += rp[(t+3) * CHAN + tid];
        }
        repr_out[(size_t)blk * CHAN + tid] = ((a0 + a1) + (a2 + a3)) * inv;
    } else {
        const int b = blk - NITER * BATCH;
        for (int k = tid; k < NPIX; k += NTHR)
            selpos[(size_t)b * NPIX + k] = 0.0f;
        __syncthreads();
        if (tid == 0) {
            #pragma unroll
            for (int t = 0; t < NITER; ++t)
                selpos[(size_t)b * NPIX + g_selind[t * BATCH + b]] += 1.0f;
        }
    }
}

// ---------------------------------------------------------------------------
extern "C" void kernel_launch(void* const* d_in, const int* in_sizes, int n_in,
                              void* d_out, int out_size) {
    const float* x = (const float*)d_in[0];
    float* out      = (float*)d_out;
    float* repr_out = out;
    float* sims_out = out + OFF_SIMS;
    float* selpos   = out + OFF_SELPOS;

    dim3 grid(NT, BATCH);
    for (int i = 0; i < NITER; ++i)
        main_kernel<<<grid, NTHR>>>(i, x, sims_out);
    final_kernel<<<NITER * BATCH + BATCH, NTHR>>>(repr_out, selpos);
}